// round 5
// baseline (speedup 1.0000x reference)
#include <cuda_runtime.h>

#define DD 512
#define NN 128
#define TPB 512
#define TINYF 1e-30f

// ---- packed f32x2 helpers (Blackwell FFMA2) ----
__device__ __forceinline__ unsigned long long fma2(unsigned long long a,
                                                   unsigned long long b,
                                                   unsigned long long c) {
    unsigned long long d;
    asm("fma.rn.f32x2 %0, %1, %2, %3;" : "=l"(d) : "l"(a), "l"(b), "l"(c));
    return d;
}
__device__ __forceinline__ float lo2(unsigned long long v) {
    return __uint_as_float((unsigned)v);
}
__device__ __forceinline__ float hi2(unsigned long long v) {
    return __uint_as_float((unsigned)(v >> 32));
}
__device__ __forceinline__ unsigned long long pack2(float x, float y) {
    unsigned long long d;
    asm("mov.b64 %0, {%1, %2};" : "=l"(d) : "f"(x), "f"(y));
    return d;
}

// Woodbury top-block sampler with DEFERRED rank-1 updates.
//
// B_i = B_{i-1} + q_{i-1} q_{i-1}^T pivinv_{i-1}.  The fused loop at step i
// folds the TWO-steps-old rank-1 (q_{i-2}, pivinv_{i-2}) and computes the
// decision-independent quantities y_i = B_{i-1} up_i and c1_i = q_{i-1}.up_i.
// The fresh pivot enters only via scalars:
//   red_i = up_i.y_i + c1_i^2 pivinv_{i-1}
//   q_i   = y_i + (c1_i pivinv_{i-1}) q_{i-1}
// so no warp ever waits on the current decision before doing FMA work.
//
// 512 threads: thread t owns row r=t&127, cols [32h,32h+32), h=t>>7,
// as 16 packed f32x2 registers.
__global__ __launch_bounds__(TPB, 1)
void slater_sampler_kernel(const float* __restrict__ P,
                           const float* __restrict__ uin,
                           float* __restrict__ out,
                           int out_size)
{
    __shared__ __align__(16) float sh_up[3][NN];
    __shared__ __align__(16) float sh_q[2][NN];   // q_{i-1}, q_{i-2} ring
    __shared__ __align__(16) float sh_y[TPB];     // y partials (h>0 slots used)
    __shared__ __align__(16) float sh_wred[16];   // per-warp up.y partials
    __shared__ __align__(16) float sh_c1[4];      // per-warp c1 partials (warps 4-7)
    __shared__ __align__(16) float sh_u[NN];

    const int tid  = threadIdx.x;
    const int lane = tid & 31;
    const int wid  = tid >> 5;
    const int r    = tid & 127;
    const int h    = tid >> 7;
    const int cbase = 32 * h;
    const int pos_base = NN * DD;

    // ---- init output: cond_probs = 0, positions = -1 ----
    {
        int n4 = out_size >> 2;
        float4* o4 = (float4*)out;
        for (int idx = tid; idx < n4; idx += TPB) {
            int base = idx * 4;
            float4 v;
            v.x = (base + 0 < pos_base) ? 0.0f : -1.0f;
            v.y = (base + 1 < pos_base) ? 0.0f : -1.0f;
            v.z = (base + 2 < pos_base) ? 0.0f : -1.0f;
            v.w = (base + 3 < pos_base) ? 0.0f : -1.0f;
            o4[idx] = v;
        }
        for (int idx = (n4 << 2) + tid; idx < out_size; idx += TPB)
            out[idx] = (idx < pos_base) ? 0.0f : -1.0f;
    }

    float pfreg = 0.0f;
    if (tid < NN) {
        sh_u[tid]     = uin[tid];
        sh_up[0][tid] = P[tid];          // P row 0
        pfreg         = P[NN + tid];     // P row 1
        sh_q[0][tid]  = 0.0f;            // q_{-2} = 0
        sh_q[1][tid]  = 0.0f;            // q_{-1} = 0
    }

    // B slice = identity
    unsigned long long rb2[16];
#pragma unroll
    for (int m = 0; m < 16; ++m) {
        unsigned long long v = 0ULL;
        int c0 = cbase + 2 * m;
        if (c0 == r)          v = 0x000000003f800000ULL;
        else if (c0 + 1 == r) v = 0x3f80000000000000ULL;
        rb2[m] = v;
    }

    __syncthreads();

    const bool write_pos = (pos_base + NN) <= out_size;

    // redundant per-thread sampler state (identical across threads)
    float ratio = 1.0f, cumul = 0.0f;
    int   k = 0;
    float piv_m1 = 0.0f;   // pivinv_{i-1}
    float piv_m2 = 0.0f;   // pivinv_{i-2}

    for (int i = 0; i < DD; ++i) {
        const float* up    = sh_up[i % 3];
        const float* qold  = sh_q[i & 1];        // q_{i-2}
        const float* qprev = sh_q[(i + 1) & 1];  // q_{i-1}

        // ---- fused: fold q_{i-2} rank-1 + matvec y_i = B_{i-1}.up_i ----
        float scale = piv_m2 * qold[r];
        unsigned long long s2 = pack2(scale, scale);
        const ulonglong2* q2 = reinterpret_cast<const ulonglong2*>(qold + cbase);
        const ulonglong2* u2 = reinterpret_cast<const ulonglong2*>(up + cbase);
        unsigned long long a0 = 0, a1 = 0, a2 = 0, a3 = 0;
#pragma unroll
        for (int j = 0; j < 4; ++j) {
            ulonglong2 qa = q2[2 * j];
            ulonglong2 qb = q2[2 * j + 1];
            ulonglong2 ua = u2[2 * j];
            ulonglong2 ub = u2[2 * j + 1];
            rb2[4 * j + 0] = fma2(s2, qa.x, rb2[4 * j + 0]);
            a0 = fma2(rb2[4 * j + 0], ua.x, a0);
            rb2[4 * j + 1] = fma2(s2, qa.y, rb2[4 * j + 1]);
            a1 = fma2(rb2[4 * j + 1], ua.y, a1);
            rb2[4 * j + 2] = fma2(s2, qb.x, rb2[4 * j + 2]);
            a2 = fma2(rb2[4 * j + 2], ub.x, a2);
            rb2[4 * j + 3] = fma2(s2, qb.y, rb2[4 * j + 3]);
            a3 = fma2(rb2[4 * j + 3], ub.y, a3);
        }
        float ypart = ((lo2(a0) + hi2(a0)) + (lo2(a1) + hi2(a1)))
                    + ((lo2(a2) + hi2(a2)) + (lo2(a3) + hi2(a3)));

        // ---- c1 partials (warps 4-7 only): c1 = q_{i-1}.up_i ----
        float c1p = 0.0f;
        if (h == 1) c1p = qprev[r] * up[r];

        // ---- per-warp reduce of up.y contribution (all warps) ----
        float contrib = up[r] * ypart;
#pragma unroll
        for (int o = 16; o; o >>= 1) {
            contrib += __shfl_xor_sync(0xffffffffu, contrib, o);
            if (h == 1) c1p += __shfl_xor_sync(0xffffffffu, c1p, o);
        }
        if (lane == 0) {
            sh_wred[wid] = contrib;
            if (h == 1) sh_c1[wid - 4] = c1p;
        }
        if (h > 0) sh_y[tid] = ypart;

        // ---- P prefetch (tid<128) ----
        if (tid < NN) {
            if (i + 1 < DD) sh_up[(i + 1) % 3][tid] = pfreg;
            if (i + 2 < DD) pfreg = P[(size_t)(i + 2) * NN + tid];
        }

        __syncthreads();   // B1: partials visible

        // ---- redundant scalar phase ----
        float uy;
        {
            const float4* w4 = reinterpret_cast<const float4*>(sh_wred);
            float4 w0 = w4[0], w1 = w4[1], w2 = w4[2], w3 = w4[3];
            uy = (((w0.x + w0.y) + (w0.z + w0.w)) + ((w1.x + w1.y) + (w1.z + w1.w)))
               + (((w2.x + w2.y) + (w2.z + w2.w)) + ((w3.x + w3.y) + (w3.z + w3.w)));
        }
        float c1;
        {
            float4 c = *reinterpret_cast<const float4*>(sh_c1);
            c1 = (c.x + c.y) + (c.z + c.w);
        }
        float red = uy + c1 * c1 * piv_m1;
        float cp  = c1 * piv_m1;

        float s = 1.0f - red;
        int last_allowed = DD - NN + k;
        float p  = -(s - 1.0f) * ratio;
        float uk = sh_u[k];
        bool occupy = ((cumul + p) >= uk) || (i == last_allowed);

        float pivot = occupy ? (s - 1.0f) : s;
        if (fabsf(pivot) < TINYF) pivot = TINYF;
        float pivinv = 1.0f / pivot;

        if (tid == 0) {
            out[k * DD + i] = p;
            if (occupy && write_pos) out[pos_base + k] = (float)i;
        }
        if (occupy) { ratio = 1.0f; cumul = 0.0f; ++k; }
        else        { ratio *= s;  cumul += p; }

        if (k == NN) break;   // all particles placed; nothing downstream

        // ---- assemble q_i into sh_q[i&1] (tid<128; h==0 keeps own ypart) ----
        if (tid < NN) {
            float qi = ((ypart + sh_y[tid + 128]) + (sh_y[tid + 256] + sh_y[tid + 384]))
                     + cp * qprev[tid];
            sh_q[i & 1][tid] = qi;
        }

        // rotate pivot-inverse history
        piv_m2 = piv_m1;
        piv_m1 = pivinv;

        __syncthreads();   // B2: q_i + next up visible
    }
}

extern "C" void kernel_launch(void* const* d_in, const int* in_sizes, int n_in,
                              void* d_out, int out_size)
{
    const float* P = (const float*)d_in[0];   // (512, 128) row-major
    const float* u = (const float*)d_in[1];   // (128,)
    float* out = (float*)d_out;
    slater_sampler_kernel<<<1, TPB>>>(P, u, out, out_size);
}